// round 8
// baseline (speedup 1.0000x reference)
#include <cuda_runtime.h>

// Inverse discrete Hough transform, round 8: coalescing-based dedup.
// Warp = 4-px strip x 256 channels; lane = (px = l>>3, cg = l&7, 16B each).
// One LDG.128 instruction covers 4 px x 32 ch; pixels sharing a rho row
// produce identical line addresses -> L1 coalescer dedups with NO serial
// dependence (replaces the predicated run-length chains of rounds 3-7).
// Pass B: angles 0..44 & 135..179, 4-px strips along y -> pBT[x*256+y][nc]
// Pass A: angles 45..134, 4-px strips along x, += pBT fold, -> out.

#define NA 180
#define NR 400
#define NC 256
#define OH 256
#define OW 256
#define AR (NA * NR)      // 72000
#define HW (OH * OW)      // 65536
#define NS4 16384         // 65536 px / 4 per strip

typedef unsigned long long ull;

__device__ float  g_accT[AR * NC];                   // 73.7 MB: [a*400+r][nc]
__device__ float2 g_trig[NA];
__device__ unsigned g_offA[(size_t)NS4 * 90 * 4];    // [strip4][arel][px] byte offs
__device__ unsigned g_offB[(size_t)NS4 * 90 * 4];
__device__ ull    g_pBT[(size_t)HW * 128];           // pass-B partial, [x*256+y][nc/2]

__device__ __forceinline__ ull fadd2(ull a, ull b) {
    ull r;
    asm("add.rn.f32x2 %0, %1, %2;" : "=l"(r) : "l"(a), "l"(b));
    return r;
}
__device__ __forceinline__ float u64lo(ull u) {
    float a, b; asm("mov.b64 {%0,%1}, %2;" : "=f"(a), "=f"(b) : "l"(u)); return a;
}
__device__ __forceinline__ float u64hi(ull u) {
    float a, b; asm("mov.b64 {%0,%1}, %2;" : "=f"(a), "=f"(b) : "l"(u)); return b;
}

__global__ void k_trig() {
    int a = threadIdx.x;
    if (a < NA) {
        // f32 theta (rn multiply), then correctly-rounded f32 cos/sin via
        // double (immune to fast-math; matches the JAX reference bit-exactly).
        float t = __fmul_rn((float)a, (float)(3.14159265358979323846 / 180.0));
        double td = (double)t;
        g_trig[a] = make_float2((float)cos(td), (float)sin(td));
    }
}

// 32x32 tiled transpose of acc[256][72000] -> g_accT[72000][256]
__global__ void k_transpose(const float* __restrict__ in) {
    __shared__ float tile[32][33];
    int tx = threadIdx.x, ty = threadIdx.y;           // 32 x 8
    int ar = blockIdx.x * 32 + tx;
#pragma unroll
    for (int k = 0; k < 4; k++)
        tile[ty + k * 8][tx] = in[(size_t)(blockIdx.y * 32 + ty + k * 8) * AR + ar];
    __syncthreads();
    int nc2 = blockIdx.y * 32 + tx;
#pragma unroll
    for (int k = 0; k < 4; k++)
        g_accT[(size_t)(blockIdx.x * 32 + ty + k * 8) * NC + nc2] = tile[tx][ty + k * 8];
}

// Precompute exact rho byte-offset tables: [strip4][arel][px].
__global__ void k_tab() {
    int idx = blockIdx.x * 256 + threadIdx.x;   // 180 * 65536 threads
    int p = idx & 3;
    int s = (idx >> 2) & (NS4 - 1);
    int a = idx >> 16;
    bool isA = (a >= 45 && a < 135);
    int line = s >> 6, q0 = (s & 63) << 2;
    int x = isA ? (q0 + p) : line;
    int y = isA ? line : (q0 + p);
    float2 cs = g_trig[a];
    // exact reference arithmetic: rn(rn(xc*cos) + rn(yc*sin)), round-half-even
    float sum = __fadd_rn(__fmul_rn((float)(x - OW / 2), cs.x),
                          __fmul_rn((float)(y - OH / 2), cs.y));
    unsigned off = (unsigned)(a * NR + __float2int_rn(sum) + NR / 2) << 10;
    int arel = isA ? (a - 45) : (a < 45 ? a : a - 90);
    unsigned* tab = isA ? g_offA : g_offB;
    tab[((size_t)s * 90 + arel) * 4 + p] = off;
}

// Main pass. CTA = 8 warps = 8 consecutive 4-px strips; tables in SMEM.
// PASS=1: y-strips, store pixel-major g_pBT (128B-contiguous per pixel).
// PASS=0: x-strips, fold g_pBT in-register, SMEM-transpose epilogue -> out.
template <int PASS>
__global__ __launch_bounds__(256, 4) void k_pass(float* __restrict__ outp) {
    __shared__ union SM {
        uint4    t4[720];            // 8 strips x 90 angles x 4 offsets
        unsigned tw[2880];
        float    stage[32 * 264];    // pass-A epilogue: 32 px x 256 ch (pad 8)
    } sm;

    const unsigned* tab = (PASS == 0) ? g_offA : g_offB;
    int tid = threadIdx.x;
    {
        const uint4* gsrc = (const uint4*)(tab + (size_t)blockIdx.x * 8 * 90 * 4);
        sm.t4[tid]       = __ldg(gsrc + tid);
        sm.t4[tid + 256] = __ldg(gsrc + tid + 256);
        if (tid < 208) sm.t4[tid + 512] = __ldg(gsrc + tid + 512);
    }
    __syncthreads();

    int w = tid >> 5, l = tid & 31;
    int pxl = l >> 3, cg = l & 7;        // pixel-in-strip, channel group
    int s = blockIdx.x * 8 + w;
    int line = s >> 6, q0 = (s & 63) << 2;

    ull base;
    {
        const char* gp = (const char*)g_accT + cg * 16;
        asm("cvta.to.global.u64 %0, %1;" : "=l"(base) : "l"(gp));
    }

    // acc[2i],acc[2i+1] = channels i*32 + cg*4 .. +3 of this lane's pixel
    ull acc[16];
#pragma unroll
    for (int i = 0; i < 16; i++) acc[i] = 0ull;

    const unsigned* tw = sm.tw + w * 360 + pxl;

    for (int a = 0; a < 90; a++) {
        unsigned off = tw[a * 4];        // broadcast LDS (8 lanes per word)
        ull addr = base + off;
#pragma unroll
        for (int i = 0; i < 8; i++) {
            ull v0, v1;
            asm("ld.global.nc.v2.u64 {%0,%1}, [%2];"
                : "=l"(v0), "=l"(v1) : "l"(addr + (unsigned)(i * 128)));
            acc[2 * i]     = fadd2(acc[2 * i],     v0);
            acc[2 * i + 1] = fadd2(acc[2 * i + 1], v1);
        }
    }

    if (PASS == 1) {
        // pixel-major staging: pix = x*256 + y = line*256 + q0 + pxl
        int pix = line * 256 + q0 + pxl;
        ull* pw = g_pBT + (size_t)pix * 128 + cg * 2;
#pragma unroll
        for (int i = 0; i < 8; i++)
            *reinterpret_cast<ulonglong2*>(pw + i * 16) =
                make_ulonglong2(acc[2 * i], acc[2 * i + 1]);
        return;
    }

    // PASS A: fold pass-B partials; lane's pixel pix = (q0+pxl)*256 + line
    {
        int pix = (q0 + pxl) * 256 + line;
        const ull* pr = g_pBT + (size_t)pix * 128 + cg * 2;
#pragma unroll
        for (int i = 0; i < 8; i++) {
            ulonglong2 b = __ldg(reinterpret_cast<const ulonglong2*>(pr + i * 16));
            acc[2 * i]     = fadd2(acc[2 * i],     b.x);
            acc[2 * i + 1] = fadd2(acc[2 * i + 1], b.y);
        }
    }

    // epilogue: stage [32 px][256 ch] in SMEM, re-read channel-major,
    // store 32 contiguous x per channel (full-line coalesced)
    __syncthreads();   // all table reads complete before overwriting union
    {
        float* st = sm.stage + (size_t)(w * 4 + pxl) * 264 + cg * 4;
#pragma unroll
        for (int i = 0; i < 8; i++)
            *reinterpret_cast<float4*>(st + i * 32) =
                make_float4(u64lo(acc[2 * i]),     u64hi(acc[2 * i]),
                            u64lo(acc[2 * i + 1]), u64hi(acc[2 * i + 1]));
    }
    __syncthreads();

    // thread tid == channel nc; CTA covers x in [X0, X0+32) at row `line`
    int X0 = (blockIdx.x & 7) << 5;
    float* op = outp + (size_t)tid * HW + (line << 8) + X0;
#pragma unroll
    for (int k = 0; k < 8; k++) {
        float4 q = make_float4(sm.stage[(size_t)(4 * k + 0) * 264 + tid],
                               sm.stage[(size_t)(4 * k + 1) * 264 + tid],
                               sm.stage[(size_t)(4 * k + 2) * 264 + tid],
                               sm.stage[(size_t)(4 * k + 3) * 264 + tid]);
        *reinterpret_cast<float4*>(op + 4 * k) = q;
    }
}

extern "C" void kernel_launch(void* const* d_in, const int* in_sizes, int n_in,
                              void* d_out, int out_size) {
    const float* acc = (const float*)d_in[0];
    float* out = (float*)d_out;

    k_trig<<<1, 192>>>();
    k_transpose<<<dim3(AR / 32, NC / 32), dim3(32, 8)>>>(acc);
    k_tab<<<NA * HW / 256, 256>>>();          // 46080 blocks
    k_pass<1><<<2048, 256>>>(out);            // pass B -> g_pBT (pixel-major)
    k_pass<0><<<2048, 256>>>(out);            // pass A: += pBT, -> out
}